// round 2
// baseline (speedup 1.0000x reference)
#include <cuda_runtime.h>
#include <cstdint>

#define CH 512
#define HW 4096
#define BATCH 2
#define NG 32
#define CPG 16
#define EPSV 1e-6f

// Scratch (allocation-free rule: __device__ globals)
__device__ float g_hn[BATCH * CH * HW];
__device__ float g_q [BATCH * CH * HW];
__device__ float g_k [BATCH * CH * HW];
__device__ float g_v [BATCH * CH * HW];
__device__ float g_s [(size_t)BATCH * HW * HW];   // 134 MB scores
__device__ float g_ao[BATCH * CH * HW];

// ---------------------------------------------------------------------------
// GroupNorm: one block per (group, batch). Group = 16 ch x 4096 px = 65536 vals
// ---------------------------------------------------------------------------
__global__ __launch_bounds__(256) void groupnorm_kernel(
    const float* __restrict__ x, const float* __restrict__ gamma,
    const float* __restrict__ beta, float* __restrict__ out)
{
    const int g = blockIdx.x;
    const int b = blockIdx.y;
    const size_t base = ((size_t)b * CH + g * CPG) * HW;
    const float* xg = x + base;

    float s = 0.f, ss = 0.f;
    for (int i = threadIdx.x; i < CPG * HW; i += 256) {
        float v = xg[i];
        s += v; ss += v * v;
    }
    // block reduce
    for (int o = 16; o; o >>= 1) {
        s  += __shfl_xor_sync(0xffffffffu, s,  o);
        ss += __shfl_xor_sync(0xffffffffu, ss, o);
    }
    __shared__ float sw[8], sw2[8];
    const int warp = threadIdx.x >> 5, lane = threadIdx.x & 31;
    if (lane == 0) { sw[warp] = s; sw2[warp] = ss; }
    __syncthreads();
    if (warp == 0) {
        s  = (lane < 8) ? sw[lane]  : 0.f;
        ss = (lane < 8) ? sw2[lane] : 0.f;
        for (int o = 4; o; o >>= 1) {
            s  += __shfl_xor_sync(0xffffffffu, s,  o);
            ss += __shfl_xor_sync(0xffffffffu, ss, o);
        }
        if (lane == 0) {
            const float n    = (float)(CPG * HW);
            const float mean = s / n;
            const float var  = ss / n - mean * mean;
            sw[0]  = mean;
            sw2[0] = rsqrtf(var + EPSV);
        }
    }
    __syncthreads();
    const float mean = sw[0], inv = sw2[0];
    for (int i = threadIdx.x; i < CPG * HW; i += 256) {
        const int c = g * CPG + (i >> 12);
        out[base + i] = (xg[i] - mean) * inv * gamma[c] + beta[c];
    }
}

// ---------------------------------------------------------------------------
// Tiled SGEMM: C[m,n] = scale * sum_k opA(m,k)*opB(k,n) (+bias[m]) (+res[m,n])
// TA=false: A[m*lda+k] (lda=K);  TA=true: A[k*lda+m] (lda=M)
// TB=false: B[k*ldb+n] (ldb=N);  TB=true: B[n*ldb+k] (ldb=K)
// BM=BN=128, BK=8, 256 threads, 8x8 per thread. All dims multiples of 128/8.
// ---------------------------------------------------------------------------
template<bool TA, bool TB, bool BIAS, bool RES>
__global__ __launch_bounds__(256) void gemm_kernel(
    const float* __restrict__ A, const float* __restrict__ Bm,
    float* __restrict__ Cm,
    const float* __restrict__ bias, const float* __restrict__ res,
    int M, int N, int K, int lda, int ldb,
    long long strideA, long long strideB, long long strideC, float scale)
{
    const int bz = blockIdx.z;
    A  += bz * strideA;
    Bm += bz * strideB;
    Cm += bz * strideC;
    const float* resb = RES ? (res + bz * strideC) : nullptr;

    const int m0 = blockIdx.y * 128;
    const int n0 = blockIdx.x * 128;

    __shared__ float As[8][128];
    __shared__ float Bs[8][128];

    const int tid = threadIdx.x;
    const int ty = tid >> 4, tx = tid & 15;
    const int ry = ty * 8, cx = tx * 8;

    float acc[8][8];
#pragma unroll
    for (int i = 0; i < 8; i++)
#pragma unroll
        for (int j = 0; j < 8; j++) acc[i][j] = 0.f;

    for (int kt = 0; kt < K; kt += 8) {
        if (!TA) {
            const int m = tid >> 1, k4 = (tid & 1) * 4;
            float4 a = *(const float4*)&A[(size_t)(m0 + m) * lda + kt + k4];
            As[k4 + 0][m] = a.x; As[k4 + 1][m] = a.y;
            As[k4 + 2][m] = a.z; As[k4 + 3][m] = a.w;
        } else {
            const int k = tid >> 5, m4 = (tid & 31) * 4;
            *(float4*)&As[k][m4] = *(const float4*)&A[(size_t)(kt + k) * lda + m0 + m4];
        }
        if (!TB) {
            const int k = tid >> 5, n4 = (tid & 31) * 4;
            *(float4*)&Bs[k][n4] = *(const float4*)&Bm[(size_t)(kt + k) * ldb + n0 + n4];
        } else {
            const int n = tid >> 1, k4 = (tid & 1) * 4;
            float4 bv = *(const float4*)&Bm[(size_t)(n0 + n) * ldb + kt + k4];
            Bs[k4 + 0][n] = bv.x; Bs[k4 + 1][n] = bv.y;
            Bs[k4 + 2][n] = bv.z; Bs[k4 + 3][n] = bv.w;
        }
        __syncthreads();
#pragma unroll
        for (int k = 0; k < 8; k++) {
            float a[8], bb[8];
            *(float4*)(a)      = *(const float4*)&As[k][ry];
            *(float4*)(a + 4)  = *(const float4*)&As[k][ry + 4];
            *(float4*)(bb)     = *(const float4*)&Bs[k][cx];
            *(float4*)(bb + 4) = *(const float4*)&Bs[k][cx + 4];
#pragma unroll
            for (int i = 0; i < 8; i++)
#pragma unroll
                for (int j = 0; j < 8; j++)
                    acc[i][j] = fmaf(a[i], bb[j], acc[i][j]);
        }
        __syncthreads();
    }

#pragma unroll
    for (int i = 0; i < 8; i++) {
        const int m = m0 + ry + i;
        const float bi = BIAS ? bias[m] : 0.f;
        const size_t cb = (size_t)m * N + n0 + cx;
#pragma unroll
        for (int j = 0; j < 8; j += 4) {
            float4 r;
            r.x = acc[i][j + 0] * scale + bi;
            r.y = acc[i][j + 1] * scale + bi;
            r.z = acc[i][j + 2] * scale + bi;
            r.w = acc[i][j + 3] * scale + bi;
            if (RES) {
                const float4 rr = *(const float4*)&resb[cb + j];
                r.x += rr.x; r.y += rr.y; r.z += rr.z; r.w += rr.w;
            }
            *(float4*)&Cm[cb + j] = r;
        }
    }
}

// ---------------------------------------------------------------------------
// Row softmax over 4096 entries, one block per row, 16 values/thread in regs
// ---------------------------------------------------------------------------
__global__ __launch_bounds__(256) void softmax_kernel(float* __restrict__ s)
{
    float* p = s + (size_t)blockIdx.x * HW;
    const int t = threadIdx.x;
    const int warp = t >> 5, lane = t & 31;
    __shared__ float sh[8];

    float v[16];
    float mx = -3.4e38f;
#pragma unroll
    for (int i = 0; i < 16; i++) {
        v[i] = p[t + i * 256];
        mx = fmaxf(mx, v[i]);
    }
    for (int o = 16; o; o >>= 1) mx = fmaxf(mx, __shfl_xor_sync(0xffffffffu, mx, o));
    if (lane == 0) sh[warp] = mx;
    __syncthreads();
    if (warp == 0) {
        float m = (lane < 8) ? sh[lane] : -3.4e38f;
        for (int o = 4; o; o >>= 1) m = fmaxf(m, __shfl_xor_sync(0xffffffffu, m, o));
        if (lane == 0) sh[0] = m;
    }
    __syncthreads();
    mx = sh[0];
    __syncthreads();   // protect sh before reuse

    float sum = 0.f;
#pragma unroll
    for (int i = 0; i < 16; i++) {
        v[i] = __expf(v[i] - mx);
        sum += v[i];
    }
    for (int o = 16; o; o >>= 1) sum += __shfl_xor_sync(0xffffffffu, sum, o);
    if (lane == 0) sh[warp] = sum;
    __syncthreads();
    if (warp == 0) {
        float m = (lane < 8) ? sh[lane] : 0.f;
        for (int o = 4; o; o >>= 1) m += __shfl_xor_sync(0xffffffffu, m, o);
        if (lane == 0) sh[0] = m;
    }
    __syncthreads();
    const float inv = 1.0f / sh[0];
#pragma unroll
    for (int i = 0; i < 16; i++) p[t + i * 256] = v[i] * inv;
}

// ---------------------------------------------------------------------------
extern "C" void kernel_launch(void* const* d_in, const int* in_sizes, int n_in,
                              void* d_out, int out_size)
{
    const float* x     = (const float*)d_in[0];
    const float* gamma = (const float*)d_in[1];
    const float* beta  = (const float*)d_in[2];
    const float* wq    = (const float*)d_in[3];
    const float* bq    = (const float*)d_in[4];
    const float* wk    = (const float*)d_in[5];
    const float* bk    = (const float*)d_in[6];
    const float* wv    = (const float*)d_in[7];
    const float* bv    = (const float*)d_in[8];
    const float* wo    = (const float*)d_in[9];
    const float* bo    = (const float*)d_in[10];
    float* out = (float*)d_out;

    float *hn, *q, *k, *v, *s, *ao;
    cudaGetSymbolAddress((void**)&hn, g_hn);
    cudaGetSymbolAddress((void**)&q,  g_q);
    cudaGetSymbolAddress((void**)&k,  g_k);
    cudaGetSymbolAddress((void**)&v,  g_v);
    cudaGetSymbolAddress((void**)&s,  g_s);
    cudaGetSymbolAddress((void**)&ao, g_ao);

    const long long sCH = (long long)CH * HW;        // per-batch stride, [C,HW]
    const long long sHW = (long long)HW * HW;        // per-batch stride, scores
    const float scale = 0.044194173824159216f;       // 1/sqrt(512)

    // 1. GroupNorm
    groupnorm_kernel<<<dim3(NG, BATCH), 256>>>(x, gamma, beta, hn);

    // 2. Q, K, V = W @ hn + b      (M=512, N=4096, K=512) NN
    dim3 gqkv(HW / 128, CH / 128, BATCH);
    gemm_kernel<false, false, true, false><<<gqkv, 256>>>(
        wq, hn, q, bq, nullptr, CH, HW, CH, CH, HW, 0, sCH, sCH, 1.f);
    gemm_kernel<false, false, true, false><<<gqkv, 256>>>(
        wk, hn, k, bk, nullptr, CH, HW, CH, CH, HW, 0, sCH, sCH, 1.f);
    gemm_kernel<false, false, true, false><<<gqkv, 256>>>(
        wv, hn, v, bv, nullptr, CH, HW, CH, CH, HW, 0, sCH, sCH, 1.f);

    // 3. scores = (Q^T K) * scale  (M=4096, N=4096, K=512) TN
    dim3 gs(HW / 128, HW / 128, BATCH);
    gemm_kernel<true, false, false, false><<<gs, 256>>>(
        q, k, s, nullptr, nullptr, HW, HW, CH, HW, HW, sCH, sCH, sHW, scale);

    // 4. softmax along last dim
    softmax_kernel<<<BATCH * HW, 256>>>(s);

    // 5. ao = V @ attn^T           (M=512, N=4096, K=4096) NT
    gemm_kernel<false, true, false, false><<<gqkv, 256>>>(
        v, s, ao, nullptr, nullptr, CH, HW, HW, HW, HW, sCH, sHW, sCH, 1.f);

    // 6. out = x + (WO @ ao + bo)  (M=512, N=4096, K=512) NN + bias + residual
    gemm_kernel<false, false, true, true><<<gqkv, 256>>>(
        wo, ao, out, bo, x, CH, HW, CH, CH, HW, 0, sCH, sCH, 1.f);
}

// round 6
// speedup vs baseline: 3.1116x; 3.1116x over previous
#include <cuda_runtime.h>
#include <cstdint>

#define CH 512
#define HW 4096
#define BATCH 2
#define NG 32
#define CPG 16
#define EPSV 1e-6f

// Scratch (allocation-free rule: __device__ globals)
__device__ float g_hn [BATCH * CH * HW];
__device__ float g_hnt[BATCH * CH * HW];   // [HW, C]
__device__ float g_qt [BATCH * CH * HW];   // [HW, C]
__device__ float g_kt [BATCH * CH * HW];   // [HW, C]
__device__ float g_v  [BATCH * CH * HW];   // [C, HW]
__device__ float g_aot[BATCH * CH * HW];   // [HW, C]
__device__ float g_s  [(size_t)BATCH * HW * HW];   // 134 MB scores

// ---------------------------------------------------------------------------
// helpers
// ---------------------------------------------------------------------------
__device__ __forceinline__ uint32_t smem_u32(const void* p) {
    uint32_t a;
    asm("{ .reg .u64 t; cvta.to.shared.u64 t, %1; cvt.u32.u64 %0, t; }"
        : "=r"(a) : "l"(p));
    return a;
}
__device__ __forceinline__ uint32_t f2tf32(float f) {
    uint32_t u;
    asm("cvt.rna.tf32.f32 %0, %1;" : "=r"(u) : "f"(f));
    return u;
}
#define CP_ASYNC16(saddr, gaddr) \
    asm volatile("cp.async.cg.shared.global [%0], [%1], 16;" \
                 :: "r"(saddr), "l"(gaddr) : "memory")
#define CP_COMMIT() asm volatile("cp.async.commit_group;" ::: "memory")
#define CP_WAIT0()  asm volatile("cp.async.wait_group 0;"  ::: "memory")

__device__ __forceinline__ void mma8(float (&d)[4], const uint32_t (&a)[4],
                                     const uint32_t (&b)[2]) {
    asm volatile(
        "mma.sync.aligned.m16n8k8.row.col.f32.tf32.tf32.f32 "
        "{%0,%1,%2,%3}, {%4,%5,%6,%7}, {%8,%9}, {%0,%1,%2,%3};"
        : "+f"(d[0]), "+f"(d[1]), "+f"(d[2]), "+f"(d[3])
        : "r"(a[0]), "r"(a[1]), "r"(a[2]), "r"(a[3]), "r"(b[0]), "r"(b[1]));
}

// ---------------------------------------------------------------------------
// GroupNorm: one block per (group, batch)
// ---------------------------------------------------------------------------
__global__ __launch_bounds__(256) void groupnorm_kernel(
    const float* __restrict__ x, const float* __restrict__ gamma,
    const float* __restrict__ beta, float* __restrict__ out)
{
    const int g = blockIdx.x;
    const int b = blockIdx.y;
    const size_t base = ((size_t)b * CH + g * CPG) * HW;
    const float* xg = x + base;

    float s = 0.f, ss = 0.f;
    for (int i = threadIdx.x; i < CPG * HW; i += 256) {
        float v = xg[i];
        s += v; ss += v * v;
    }
    for (int o = 16; o; o >>= 1) {
        s  += __shfl_xor_sync(0xffffffffu, s,  o);
        ss += __shfl_xor_sync(0xffffffffu, ss, o);
    }
    __shared__ float sw[8], sw2[8];
    const int warp = threadIdx.x >> 5, lane = threadIdx.x & 31;
    if (lane == 0) { sw[warp] = s; sw2[warp] = ss; }
    __syncthreads();
    if (warp == 0) {
        s  = (lane < 8) ? sw[lane]  : 0.f;
        ss = (lane < 8) ? sw2[lane] : 0.f;
        for (int o = 4; o; o >>= 1) {
            s  += __shfl_xor_sync(0xffffffffu, s,  o);
            ss += __shfl_xor_sync(0xffffffffu, ss, o);
        }
        if (lane == 0) {
            const float n    = (float)(CPG * HW);
            const float mean = s / n;
            const float var  = ss / n - mean * mean;
            sw[0]  = mean;
            sw2[0] = rsqrtf(var + EPSV);
        }
    }
    __syncthreads();
    const float mean = sw[0], inv = sw2[0];
    for (int i = threadIdx.x; i < CPG * HW; i += 256) {
        const int c = g * CPG + (i >> 12);
        out[base + i] = (xg[i] - mean) * inv * gamma[c] + beta[c];
    }
}

// ---------------------------------------------------------------------------
// Transpose [C, HW] -> [HW, C] per batch
// ---------------------------------------------------------------------------
__global__ __launch_bounds__(256) void transpose_kernel(
    const float* __restrict__ in, float* __restrict__ out)
{
    __shared__ float tile[32][33];
    const int b = blockIdx.z;
    in  += (size_t)b * CH * HW;
    out += (size_t)b * CH * HW;
    const int p0 = blockIdx.x * 32, c0 = blockIdx.y * 32;
    const int tx = threadIdx.x & 31, ty = threadIdx.x >> 5;
#pragma unroll
    for (int i = 0; i < 32; i += 8)
        tile[ty + i][tx] = in[(size_t)(c0 + ty + i) * HW + p0 + tx];
    __syncthreads();
#pragma unroll
    for (int i = 0; i < 32; i += 8)
        out[(size_t)(p0 + ty + i) * CH + c0 + tx] = tile[tx][ty + i];
}

// ---------------------------------------------------------------------------
// tf32 mma.sync GEMM: D = scale * A(M,K) . B(N,K)^T  (+epilogue)
// MODE: 0=scale only, 1=+bias[n], 2=+bias[m], 3=+bias[m]+res[m,n]
// 128x128 CTA tile, BK=16, 256 threads, warp tile 64x32 (warps 2m x 4n).
// ---------------------------------------------------------------------------
template<int MODE>
__global__ __launch_bounds__(256, 2) void mma_gemm(
    const float* __restrict__ A, const float* __restrict__ B,
    float* __restrict__ C,
    const float* __restrict__ bias, const float* __restrict__ res,
    int K, int lda, int ldb, int ldc,
    long long sA, long long sB, long long sC, float scale)
{
    __shared__ float As[2][128][20];   // padded stride 20: conflict-free frags
    __shared__ float Bs[2][128][20];

    const int tid = threadIdx.x, lane = tid & 31, wid = tid >> 5;
    const int wm = wid & 1, wn = wid >> 1;          // warp grid 2 x 4
    const int grp = lane >> 2, tig = lane & 3;
    const int bz = blockIdx.z;
    A += bz * sA; B += bz * sB; C += bz * sC;
    const float* resb = (MODE == 3) ? res + bz * sC : nullptr;
    const int m0 = blockIdx.y * 128, n0 = blockIdx.x * 128;

    // cp.async mapping: thread -> rows (tid>>2, +64), k-cols (tid&3)*4
    const int lr = tid >> 2;
    const int lc = (tid & 3) * 4;
    const float* Ag0 = A + (size_t)(m0 + lr) * lda + lc;
    const float* Ag1 = Ag0 + (size_t)64 * lda;
    const float* Bg0 = B + (size_t)(n0 + lr) * ldb + lc;
    const float* Bg1 = Bg0 + (size_t)64 * ldb;
    uint32_t sa[2], sb[2];
    sa[0] = smem_u32(&As[0][lr][lc]);
    sa[1] = smem_u32(&As[1][lr][lc]);
    sb[0] = smem_u32(&Bs[0][lr][lc]);
    sb[1] = smem_u32(&Bs[1][lr][lc]);
    const uint32_t roff = 64 * 20 * 4;

    float acc[4][4][4];
#pragma unroll
    for (int mt = 0; mt < 4; mt++)
#pragma unroll
        for (int nt = 0; nt < 4; nt++)
#pragma unroll
            for (int j = 0; j < 4; j++) acc[mt][nt][j] = 0.f;

    // prologue: tile 0
    CP_ASYNC16(sa[0],        Ag0);
    CP_ASYNC16(sa[0] + roff, Ag1);
    CP_ASYNC16(sb[0],        Bg0);
    CP_ASYNC16(sb[0] + roff, Bg1);
    CP_COMMIT();
    CP_WAIT0();
    __syncthreads();

    const int T = K >> 4;
    for (int kt = 0; kt < T; kt++) {
        const int cur = kt & 1, nxt = cur ^ 1;
        if (kt + 1 < T) {
            const size_t ko = (size_t)(kt + 1) * 16;
            CP_ASYNC16(sa[nxt],        Ag0 + ko);
            CP_ASYNC16(sa[nxt] + roff, Ag1 + ko);
            CP_ASYNC16(sb[nxt],        Bg0 + ko);
            CP_ASYNC16(sb[nxt] + roff, Bg1 + ko);
            CP_COMMIT();
        }
#pragma unroll
        for (int ks = 0; ks < 2; ks++) {
            const int c0 = ks * 8 + tig;
            uint32_t af[4][4], bf[4][2];
#pragma unroll
            for (int mt = 0; mt < 4; mt++) {
                const int r = wm * 64 + mt * 16 + grp;
                af[mt][0] = f2tf32(As[cur][r    ][c0]);
                af[mt][1] = f2tf32(As[cur][r + 8][c0]);
                af[mt][2] = f2tf32(As[cur][r    ][c0 + 4]);
                af[mt][3] = f2tf32(As[cur][r + 8][c0 + 4]);
            }
#pragma unroll
            for (int nt = 0; nt < 4; nt++) {
                const int r = wn * 32 + nt * 8 + grp;
                bf[nt][0] = f2tf32(Bs[cur][r][c0]);
                bf[nt][1] = f2tf32(Bs[cur][r][c0 + 4]);
            }
#pragma unroll
            for (int mt = 0; mt < 4; mt++)
#pragma unroll
                for (int nt = 0; nt < 4; nt++)
                    mma8(acc[mt][nt], af[mt], bf[nt]);
        }
        if (kt + 1 < T) CP_WAIT0();
        __syncthreads();
    }

    // Epilogue
#pragma unroll
    for (int mt = 0; mt < 4; mt++) {
        const int r0 = m0 + wm * 64 + mt * 16 + grp;
        float bm0 = 0.f, bm1 = 0.f;
        if (MODE == 2 || MODE == 3) { bm0 = bias[r0]; bm1 = bias[r0 + 8]; }
#pragma unroll
        for (int nt = 0; nt < 4; nt++) {
            const int c = n0 + wn * 32 + nt * 8 + tig * 2;
            const float* d = acc[mt][nt];
            float2 o0 = { d[0] * scale, d[1] * scale };
            float2 o1 = { d[2] * scale, d[3] * scale };
            if (MODE == 1) {
                const float2 bn = *(const float2*)&bias[c];
                o0.x += bn.x; o0.y += bn.y; o1.x += bn.x; o1.y += bn.y;
            }
            if (MODE == 2 || MODE == 3) {
                o0.x += bm0; o0.y += bm0; o1.x += bm1; o1.y += bm1;
            }
            const size_t i0 = (size_t)r0 * ldc + c;
            const size_t i1 = (size_t)(r0 + 8) * ldc + c;
            if (MODE == 3) {
                const float2 r0v = *(const float2*)&resb[i0];
                const float2 r1v = *(const float2*)&resb[i1];
                o0.x += r0v.x; o0.y += r0v.y; o1.x += r1v.x; o1.y += r1v.y;
            }
            *(float2*)&C[i0] = o0;
            *(float2*)&C[i1] = o1;
        }
    }
}

// ---------------------------------------------------------------------------
// Row softmax over 4096 entries
// ---------------------------------------------------------------------------
__global__ __launch_bounds__(256) void softmax_kernel(float* __restrict__ s)
{
    float* p = s + (size_t)blockIdx.x * HW;
    const int t = threadIdx.x;
    const int warp = t >> 5, lane = t & 31;
    __shared__ float sh[8];

    float v[16];
    float mx = -3.4e38f;
#pragma unroll
    for (int i = 0; i < 16; i++) {
        v[i] = p[t + i * 256];
        mx = fmaxf(mx, v[i]);
    }
    for (int o = 16; o; o >>= 1) mx = fmaxf(mx, __shfl_xor_sync(0xffffffffu, mx, o));
    if (lane == 0) sh[warp] = mx;
    __syncthreads();
    if (warp == 0) {
        float m = (lane < 8) ? sh[lane] : -3.4e38f;
        for (int o = 4; o; o >>= 1) m = fmaxf(m, __shfl_xor_sync(0xffffffffu, m, o));
        if (lane == 0) sh[0] = m;
    }
    __syncthreads();
    mx = sh[0];
    __syncthreads();

    float sum = 0.f;
#pragma unroll
    for (int i = 0; i < 16; i++) {
        v[i] = __expf(v[i] - mx);
        sum += v[i];
    }
    for (int o = 16; o; o >>= 1) sum += __shfl_xor_sync(0xffffffffu, sum, o);
    if (lane == 0) sh[warp] = sum;
    __syncthreads();
    if (warp == 0) {
        float m = (lane < 8) ? sh[lane] : 0.f;
        for (int o = 4; o; o >>= 1) m += __shfl_xor_sync(0xffffffffu, m, o);
        if (lane == 0) sh[0] = m;
    }
    __syncthreads();
    const float inv = 1.0f / sh[0];
#pragma unroll
    for (int i = 0; i < 16; i++) p[t + i * 256] = v[i] * inv;
}

// ---------------------------------------------------------------------------
extern "C" void kernel_launch(void* const* d_in, const int* in_sizes, int n_in,
                              void* d_out, int out_size)
{
    const float* x     = (const float*)d_in[0];
    const float* gamma = (const float*)d_in[1];
    const float* beta  = (const float*)d_in[2];
    const float* wq    = (const float*)d_in[3];
    const float* bq    = (const float*)d_in[4];
    const float* wk    = (const float*)d_in[5];
    const float* bk    = (const float*)d_in[6];
    const float* wv    = (const float*)d_in[7];
    const float* bv    = (const float*)d_in[8];
    const float* wo    = (const float*)d_in[9];
    const float* bo    = (const float*)d_in[10];
    float* out = (float*)d_out;

    float *hn, *hnt, *qt, *kt, *v, *aot, *s;
    cudaGetSymbolAddress((void**)&hn,  g_hn);
    cudaGetSymbolAddress((void**)&hnt, g_hnt);
    cudaGetSymbolAddress((void**)&qt,  g_qt);
    cudaGetSymbolAddress((void**)&kt,  g_kt);
    cudaGetSymbolAddress((void**)&v,   g_v);
    cudaGetSymbolAddress((void**)&aot, g_aot);
    cudaGetSymbolAddress((void**)&s,   g_s);

    const long long sCH = (long long)CH * HW;
    const long long sHW = (long long)HW * HW;
    const float scale = 0.044194173824159216f;   // 1/sqrt(512)

    // 1. GroupNorm -> hn [C, HW]
    groupnorm_kernel<<<dim3(NG, BATCH), 256>>>(x, gamma, beta, hn);
    // 2. hn -> hnt [HW, C]
    transpose_kernel<<<dim3(HW / 32, CH / 32, BATCH), 256>>>(hn, hnt);

    // 3. q_t[p,o] = hnt . Wq^T + bq[o]   (M=4096, N=512, K=512)
    mma_gemm<1><<<dim3(CH / 128, HW / 128, BATCH), 256>>>(
        hnt, wq, qt, bq, nullptr, CH, CH, CH, CH, sCH, 0, sCH, 1.f);
    mma_gemm<1><<<dim3(CH / 128, HW / 128, BATCH), 256>>>(
        hnt, wk, kt, bk, nullptr, CH, CH, CH, CH, sCH, 0, sCH, 1.f);
    // 4. v[c,p] = Wv . hnt^T + bv[c]     (M=512, N=4096, K=512)
    mma_gemm<2><<<dim3(HW / 128, CH / 128, BATCH), 256>>>(
        wv, hnt, v, bv, nullptr, CH, CH, CH, HW, 0, sCH, sCH, 1.f);

    // 5. s[i,j] = (q_t . k_t^T) * scale  (M=4096, N=4096, K=512)
    mma_gemm<0><<<dim3(HW / 128, HW / 128, BATCH), 256>>>(
        qt, kt, s, nullptr, nullptr, CH, CH, CH, HW, sCH, sCH, sHW, scale);

    // 6. softmax rows
    softmax_kernel<<<BATCH * HW, 256>>>(s);

    // 7. ao_t[i,c] = attn . v^T          (M=4096, N=512, K=4096)
    mma_gemm<0><<<dim3(CH / 128, HW / 128, BATCH), 256>>>(
        s, v, aot, nullptr, nullptr, HW, HW, HW, CH, sHW, sCH, sCH, 1.f);

    // 8. out[o,p] = Wo . ao_t^T + bo[o] + x   (M=512, N=4096, K=512)
    mma_gemm<3><<<dim3(HW / 128, CH / 128, BATCH), 256>>>(
        wo, aot, out, bo, x, CH, CH, CH, HW, 0, sCH, sCH, 1.f);
}

// round 7
// speedup vs baseline: 3.1451x; 1.0108x over previous
#include <cuda_runtime.h>
#include <cstdint>

#define CH 512
#define HW 4096
#define BATCH 2
#define NG 32
#define CPG 16
#define EPSV 1e-6f

// Scratch (allocation-free rule: __device__ globals)
__device__ float g_hn [BATCH * CH * HW];
__device__ float g_hnt[BATCH * CH * HW];   // [HW, C] tf32-rounded
__device__ float g_qt [BATCH * CH * HW];   // [HW, C] tf32-rounded
__device__ float g_kt [BATCH * CH * HW];   // [HW, C] tf32-rounded
__device__ float g_v  [BATCH * CH * HW];   // [C, HW] tf32-rounded
__device__ float g_aot[BATCH * CH * HW];   // [HW, C] tf32-rounded
__device__ float g_s  [(size_t)BATCH * HW * HW];   // 134 MB scores
__device__ float g_wr [4 * CH * CH];       // tf32-rounded weights q,k,v,o

// ---------------------------------------------------------------------------
// helpers
// ---------------------------------------------------------------------------
__device__ __forceinline__ uint32_t smem_u32(const void* p) {
    uint32_t a;
    asm("{ .reg .u64 t; cvta.to.shared.u64 t, %1; cvt.u32.u64 %0, t; }"
        : "=r"(a) : "l"(p));
    return a;
}
__device__ __forceinline__ float f2tf32f(float f) {
    uint32_t u;
    asm("cvt.rna.tf32.f32 %0, %1;" : "=r"(u) : "f"(f));
    return __uint_as_float(u);
}
#define CP_ASYNC16(saddr, gaddr) \
    asm volatile("cp.async.cg.shared.global [%0], [%1], 16;" \
                 :: "r"(saddr), "l"(gaddr) : "memory")
#define CP_COMMIT() asm volatile("cp.async.commit_group;" ::: "memory")
#define CP_WAIT0()  asm volatile("cp.async.wait_group 0;"  ::: "memory")
#define CP_WAIT1()  asm volatile("cp.async.wait_group 1;"  ::: "memory")

__device__ __forceinline__ void mma8(float (&d)[4], const uint32_t (&a)[4],
                                     const uint32_t (&b)[2]) {
    asm volatile(
        "mma.sync.aligned.m16n8k8.row.col.f32.tf32.tf32.f32 "
        "{%0,%1,%2,%3}, {%4,%5,%6,%7}, {%8,%9}, {%0,%1,%2,%3};"
        : "+f"(d[0]), "+f"(d[1]), "+f"(d[2]), "+f"(d[3])
        : "r"(a[0]), "r"(a[1]), "r"(a[2]), "r"(a[3]), "r"(b[0]), "r"(b[1]));
}

// ---------------------------------------------------------------------------
// Pre-round weights to tf32 (once per launch, 4 matrices concatenated)
// ---------------------------------------------------------------------------
__global__ __launch_bounds__(256) void round_copy_kernel(
    const float* __restrict__ w0, const float* __restrict__ w1,
    const float* __restrict__ w2, const float* __restrict__ w3,
    float* __restrict__ out)
{
    const int n4 = CH * CH / 4;   // float4 count per matrix
    for (int i = blockIdx.x * 256 + threadIdx.x; i < 4 * n4; i += gridDim.x * 256) {
        const int m = i / n4, j = i - m * n4;
        const float* src = (m == 0) ? w0 : (m == 1) ? w1 : (m == 2) ? w2 : w3;
        float4 v = ((const float4*)src)[j];
        v.x = f2tf32f(v.x); v.y = f2tf32f(v.y);
        v.z = f2tf32f(v.z); v.w = f2tf32f(v.w);
        ((float4*)out)[i] = v;
    }
}

// ---------------------------------------------------------------------------
// GroupNorm: one block per (group, batch)
// ---------------------------------------------------------------------------
__global__ __launch_bounds__(256) void groupnorm_kernel(
    const float* __restrict__ x, const float* __restrict__ gamma,
    const float* __restrict__ beta, float* __restrict__ out)
{
    const int g = blockIdx.x;
    const int b = blockIdx.y;
    const size_t base = ((size_t)b * CH + g * CPG) * HW;
    const float* xg = x + base;

    float s = 0.f, ss = 0.f;
    for (int i = threadIdx.x; i < CPG * HW; i += 256) {
        float v = xg[i];
        s += v; ss += v * v;
    }
    for (int o = 16; o; o >>= 1) {
        s  += __shfl_xor_sync(0xffffffffu, s,  o);
        ss += __shfl_xor_sync(0xffffffffu, ss, o);
    }
    __shared__ float sw[8], sw2[8];
    const int warp = threadIdx.x >> 5, lane = threadIdx.x & 31;
    if (lane == 0) { sw[warp] = s; sw2[warp] = ss; }
    __syncthreads();
    if (warp == 0) {
        s  = (lane < 8) ? sw[lane]  : 0.f;
        ss = (lane < 8) ? sw2[lane] : 0.f;
        for (int o = 4; o; o >>= 1) {
            s  += __shfl_xor_sync(0xffffffffu, s,  o);
            ss += __shfl_xor_sync(0xffffffffu, ss, o);
        }
        if (lane == 0) {
            const float n    = (float)(CPG * HW);
            const float mean = s / n;
            const float var  = ss / n - mean * mean;
            sw[0]  = mean;
            sw2[0] = rsqrtf(var + EPSV);
        }
    }
    __syncthreads();
    const float mean = sw[0], inv = sw2[0];
    for (int i = threadIdx.x; i < CPG * HW; i += 256) {
        const int c = g * CPG + (i >> 12);
        out[base + i] = (xg[i] - mean) * inv * gamma[c] + beta[c];
    }
}

// ---------------------------------------------------------------------------
// Transpose [C, HW] -> [HW, C] per batch, tf32-rounded output
// ---------------------------------------------------------------------------
__global__ __launch_bounds__(256) void transpose_kernel(
    const float* __restrict__ in, float* __restrict__ out)
{
    __shared__ float tile[32][33];
    const int b = blockIdx.z;
    in  += (size_t)b * CH * HW;
    out += (size_t)b * CH * HW;
    const int p0 = blockIdx.x * 32, c0 = blockIdx.y * 32;
    const int tx = threadIdx.x & 31, ty = threadIdx.x >> 5;
#pragma unroll
    for (int i = 0; i < 32; i += 8)
        tile[ty + i][tx] = in[(size_t)(c0 + ty + i) * HW + p0 + tx];
    __syncthreads();
#pragma unroll
    for (int i = 0; i < 32; i += 8)
        out[(size_t)(p0 + ty + i) * CH + c0 + tx] = f2tf32f(tile[tx][ty + i]);
}

// ---------------------------------------------------------------------------
// tf32 mma.sync GEMM: D = scale * A(M,K) . B(N,K)^T  (+epilogue)
// Operands must already be tf32-rounded (no cvt in mainloop).
// MODE: 0=scale only, 1=+bias[n], 2=+bias[m], 3=+bias[m]+res[m,n]
// ROUND: 1 -> round output to tf32 (it feeds another GEMM)
// 128x128 CTA tile, BK=16, 3-stage cp.async, 256 threads, warp tile 64x32.
// ---------------------------------------------------------------------------
#define STG_F (128 * 20)          // floats per stage per operand
template<int MODE, int ROUND>
__global__ __launch_bounds__(256, 2) void mma_gemm(
    const float* __restrict__ A, const float* __restrict__ B,
    float* __restrict__ C,
    const float* __restrict__ bias, const float* __restrict__ res,
    int K, int lda, int ldb, int ldc,
    long long sA, long long sB, long long sC, float scale)
{
    extern __shared__ float sm[];
    float* As = sm;                 // [3][128][20]
    float* Bs = sm + 3 * STG_F;

    const int tid = threadIdx.x, lane = tid & 31, wid = tid >> 5;
    const int wm = wid & 1, wn = wid >> 1;          // warp grid 2 x 4
    const int grp = lane >> 2, tig = lane & 3;
    const int bz = blockIdx.z;
    A += bz * sA; B += bz * sB; C += bz * sC;
    const float* resb = (MODE == 3) ? res + bz * sC : nullptr;
    const int m0 = blockIdx.y * 128, n0 = blockIdx.x * 128;

    // cp.async mapping: thread -> rows (tid>>2, +64), k-cols (tid&3)*4
    const int lr = tid >> 2;
    const int lc = (tid & 3) * 4;
    const float* Ag0 = A + (size_t)(m0 + lr) * lda + lc;
    const float* Ag1 = Ag0 + (size_t)64 * lda;
    const float* Bg0 = B + (size_t)(n0 + lr) * ldb + lc;
    const float* Bg1 = Bg0 + (size_t)64 * ldb;
    const uint32_t sa0 = smem_u32(As) + (uint32_t)(lr * 20 + lc) * 4;
    const uint32_t sb0 = smem_u32(Bs) + (uint32_t)(lr * 20 + lc) * 4;
    const uint32_t roff = 64 * 20 * 4;      // +64 rows
    const uint32_t soff = STG_F * 4;        // stage stride bytes

    float acc[4][4][4];
#pragma unroll
    for (int mt = 0; mt < 4; mt++)
#pragma unroll
        for (int nt = 0; nt < 4; nt++)
#pragma unroll
            for (int j = 0; j < 4; j++) acc[mt][nt][j] = 0.f;

    const int T = K >> 4;

    // prologue: stages 0,1
#pragma unroll
    for (int p = 0; p < 2; p++) {
        const size_t ko = (size_t)p * 16;
        CP_ASYNC16(sa0 + p * soff,        Ag0 + ko);
        CP_ASYNC16(sa0 + p * soff + roff, Ag1 + ko);
        CP_ASYNC16(sb0 + p * soff,        Bg0 + ko);
        CP_ASYNC16(sb0 + p * soff + roff, Bg1 + ko);
        CP_COMMIT();
    }

    int cur = 0, nxt_issue = 2;
    for (int kt = 0; kt < T; kt++) {
        if (kt + 1 < T) CP_WAIT1(); else CP_WAIT0();
        __syncthreads();

        const float* Ac = As + cur * STG_F;
        const float* Bc = Bs + cur * STG_F;
#pragma unroll
        for (int ks = 0; ks < 2; ks++) {
            const int c0 = ks * 8 + tig;
            uint32_t af[4][4], bf[4][2];
#pragma unroll
            for (int mt = 0; mt < 4; mt++) {
                const int r = wm * 64 + mt * 16 + grp;
                af[mt][0] = __float_as_uint(Ac[(r    ) * 20 + c0]);
                af[mt][1] = __float_as_uint(Ac[(r + 8) * 20 + c0]);
                af[mt][2] = __float_as_uint(Ac[(r    ) * 20 + c0 + 4]);
                af[mt][3] = __float_as_uint(Ac[(r + 8) * 20 + c0 + 4]);
            }
#pragma unroll
            for (int nt = 0; nt < 4; nt++) {
                const int r = wn * 32 + nt * 8 + grp;
                bf[nt][0] = __float_as_uint(Bc[r * 20 + c0]);
                bf[nt][1] = __float_as_uint(Bc[r * 20 + c0 + 4]);
            }
#pragma unroll
            for (int mt = 0; mt < 4; mt++)
#pragma unroll
                for (int nt = 0; nt < 4; nt++)
                    mma8(acc[mt][nt], af[mt], bf[nt]);
        }

        if (kt + 2 < T) {
            const size_t ko = (size_t)(kt + 2) * 16;
            const uint32_t st = nxt_issue * soff;
            CP_ASYNC16(sa0 + st,        Ag0 + ko);
            CP_ASYNC16(sa0 + st + roff, Ag1 + ko);
            CP_ASYNC16(sb0 + st,        Bg0 + ko);
            CP_ASYNC16(sb0 + st + roff, Bg1 + ko);
            CP_COMMIT();
        }
        cur = (cur + 1 == 3) ? 0 : cur + 1;
        nxt_issue = (nxt_issue + 1 == 3) ? 0 : nxt_issue + 1;
    }

    // Epilogue
#pragma unroll
    for (int mt = 0; mt < 4; mt++) {
        const int r0 = m0 + wm * 64 + mt * 16 + grp;
        float bm0 = 0.f, bm1 = 0.f;
        if (MODE == 2 || MODE == 3) { bm0 = bias[r0]; bm1 = bias[r0 + 8]; }
#pragma unroll
        for (int nt = 0; nt < 4; nt++) {
            const int c = n0 + wn * 32 + nt * 8 + tig * 2;
            const float* d = acc[mt][nt];
            float2 o0 = { d[0] * scale, d[1] * scale };
            float2 o1 = { d[2] * scale, d[3] * scale };
            if (MODE == 1) {
                const float2 bn = *(const float2*)&bias[c];
                o0.x += bn.x; o0.y += bn.y; o1.x += bn.x; o1.y += bn.y;
            }
            if (MODE == 2 || MODE == 3) {
                o0.x += bm0; o0.y += bm0; o1.x += bm1; o1.y += bm1;
            }
            const size_t i0 = (size_t)r0 * ldc + c;
            const size_t i1 = (size_t)(r0 + 8) * ldc + c;
            if (MODE == 3) {
                const float2 r0v = *(const float2*)&resb[i0];
                const float2 r1v = *(const float2*)&resb[i1];
                o0.x += r0v.x; o0.y += r0v.y; o1.x += r1v.x; o1.y += r1v.y;
            }
            if (ROUND) {
                o0.x = f2tf32f(o0.x); o0.y = f2tf32f(o0.y);
                o1.x = f2tf32f(o1.x); o1.y = f2tf32f(o1.y);
            }
            *(float2*)&C[i0] = o0;
            *(float2*)&C[i1] = o1;
        }
    }
}

// ---------------------------------------------------------------------------
// Row softmax over 4096 entries, float4 I/O, tf32-rounded output
// ---------------------------------------------------------------------------
__global__ __launch_bounds__(256) void softmax_kernel(float* __restrict__ s)
{
    float4* p = (float4*)(s + (size_t)blockIdx.x * HW);
    const int t = threadIdx.x;
    const int warp = t >> 5, lane = t & 31;
    __shared__ float sh[8];

    float4 v[4];
    float mx = -3.4e38f;
#pragma unroll
    for (int i = 0; i < 4; i++) {
        v[i] = p[t + i * 256];
        mx = fmaxf(mx, fmaxf(fmaxf(v[i].x, v[i].y), fmaxf(v[i].z, v[i].w)));
    }
    for (int o = 16; o; o >>= 1) mx = fmaxf(mx, __shfl_xor_sync(0xffffffffu, mx, o));
    if (lane == 0) sh[warp] = mx;
    __syncthreads();
    if (warp == 0) {
        float m = (lane < 8) ? sh[lane] : -3.4e38f;
        for (int o = 4; o; o >>= 1) m = fmaxf(m, __shfl_xor_sync(0xffffffffu, m, o));
        if (lane == 0) sh[0] = m;
    }
    __syncthreads();
    mx = sh[0];
    __syncthreads();

    float sum = 0.f;
#pragma unroll
    for (int i = 0; i < 4; i++) {
        v[i].x = __expf(v[i].x - mx);
        v[i].y = __expf(v[i].y - mx);
        v[i].z = __expf(v[i].z - mx);
        v[i].w = __expf(v[i].w - mx);
        sum += v[i].x + v[i].y + v[i].z + v[i].w;
    }
    for (int o = 16; o; o >>= 1) sum += __shfl_xor_sync(0xffffffffu, sum, o);
    if (lane == 0) sh[warp] = sum;
    __syncthreads();
    if (warp == 0) {
        float m = (lane < 8) ? sh[lane] : 0.f;
        for (int o = 4; o; o >>= 1) m += __shfl_xor_sync(0xffffffffu, m, o);
        if (lane == 0) sh[0] = m;
    }
    __syncthreads();
    const float inv = 1.0f / sh[0];
#pragma unroll
    for (int i = 0; i < 4; i++) {
        v[i].x = f2tf32f(v[i].x * inv);
        v[i].y = f2tf32f(v[i].y * inv);
        v[i].z = f2tf32f(v[i].z * inv);
        v[i].w = f2tf32f(v[i].w * inv);
        p[t + i * 256] = v[i];
    }
}

// ---------------------------------------------------------------------------
extern "C" void kernel_launch(void* const* d_in, const int* in_sizes, int n_in,
                              void* d_out, int out_size)
{
    const float* x     = (const float*)d_in[0];
    const float* gamma = (const float*)d_in[1];
    const float* beta  = (const float*)d_in[2];
    const float* wq    = (const float*)d_in[3];
    const float* bq    = (const float*)d_in[4];
    const float* wk    = (const float*)d_in[5];
    const float* bk    = (const float*)d_in[6];
    const float* wv    = (const float*)d_in[7];
    const float* bv    = (const float*)d_in[8];
    const float* wo    = (const float*)d_in[9];
    const float* bo    = (const float*)d_in[10];
    float* out = (float*)d_out;

    float *hn, *hnt, *qt, *kt, *v, *aot, *s, *wr;
    cudaGetSymbolAddress((void**)&hn,  g_hn);
    cudaGetSymbolAddress((void**)&hnt, g_hnt);
    cudaGetSymbolAddress((void**)&qt,  g_qt);
    cudaGetSymbolAddress((void**)&kt,  g_kt);
    cudaGetSymbolAddress((void**)&v,   g_v);
    cudaGetSymbolAddress((void**)&aot, g_aot);
    cudaGetSymbolAddress((void**)&s,   g_s);
    cudaGetSymbolAddress((void**)&wr,  g_wr);
    const float* wqr = wr;
    const float* wkr = wr + CH * CH;
    const float* wvr = wr + 2 * CH * CH;
    const float* wor = wr + 3 * CH * CH;

    const int SMEM = 2 * 3 * STG_F * 4;   // 61440 B
    static int smem_set = 0;
    if (!smem_set) {
        cudaFuncSetAttribute(mma_gemm<1,1>, cudaFuncAttributeMaxDynamicSharedMemorySize, SMEM);
        cudaFuncSetAttribute(mma_gemm<2,1>, cudaFuncAttributeMaxDynamicSharedMemorySize, SMEM);
        cudaFuncSetAttribute(mma_gemm<0,0>, cudaFuncAttributeMaxDynamicSharedMemorySize, SMEM);
        cudaFuncSetAttribute(mma_gemm<0,1>, cudaFuncAttributeMaxDynamicSharedMemorySize, SMEM);
        cudaFuncSetAttribute(mma_gemm<3,0>, cudaFuncAttributeMaxDynamicSharedMemorySize, SMEM);
        smem_set = 1;
    }

    const long long sCH = (long long)CH * HW;
    const long long sHW = (long long)HW * HW;
    const float scale = 0.044194173824159216f;   // 1/sqrt(512)

    // 0. tf32-round weights
    round_copy_kernel<<<256, 256>>>(wq, wk, wv, wo, wr);
    // 1. GroupNorm -> hn [C, HW]
    groupnorm_kernel<<<dim3(NG, BATCH), 256>>>(x, gamma, beta, hn);
    // 2. hn -> hnt [HW, C] (rounded)
    transpose_kernel<<<dim3(HW / 32, CH / 32, BATCH), 256>>>(hn, hnt);

    // 3. q_t[p,o] = hnt . Wq^T + bq[o]   (M=4096, N=512, K=512)
    mma_gemm<1,1><<<dim3(CH / 128, HW / 128, BATCH), 256, SMEM>>>(
        hnt, wqr, qt, bq, nullptr, CH, CH, CH, CH, sCH, 0, sCH, 1.f);
    mma_gemm<1,1><<<dim3(CH / 128, HW / 128, BATCH), 256, SMEM>>>(
        hnt, wkr, kt, bk, nullptr, CH, CH, CH, CH, sCH, 0, sCH, 1.f);
    // 4. v[c,p] = Wv . hnt^T + bv[c]     (M=512, N=4096, K=512)
    mma_gemm<2,1><<<dim3(HW / 128, CH / 128, BATCH), 256, SMEM>>>(
        wvr, hnt, v, bv, nullptr, CH, CH, CH, HW, 0, sCH, sCH, 1.f);

    // 5. s[i,j] = (q_t . k_t^T) * scale  (M=4096, N=4096, K=512)
    mma_gemm<0,0><<<dim3(HW / 128, HW / 128, BATCH), 256, SMEM>>>(
        qt, kt, s, nullptr, nullptr, CH, CH, CH, HW, sCH, sCH, sHW, scale);

    // 6. softmax rows (rounded output)
    softmax_kernel<<<BATCH * HW, 256>>>(s);

    // 7. ao_t[i,c] = attn . v^T          (M=4096, N=512, K=4096)
    mma_gemm<0,1><<<dim3(CH / 128, HW / 128, BATCH), 256, SMEM>>>(
        s, v, aot, nullptr, nullptr, HW, HW, HW, CH, sHW, sCH, sCH, 1.f);

    // 8. out[o,p] = Wo . ao_t^T + bo[o] + x   (M=512, N=4096, K=512)
    mma_gemm<3,0><<<dim3(HW / 128, CH / 128, BATCH), 256, SMEM>>>(
        wor, aot, out, bo, x, CH, CH, CH, HW, 0, sCH, sCH, 1.f);
}

// round 8
// speedup vs baseline: 5.6172x; 1.7861x over previous
#include <cuda_runtime.h>
#include <cuda_bf16.h>
#include <cstdint>

#define CH 512
#define HW 4096
#define BATCH 2
#define NG 32
#define CPG 16
#define EPSV 1e-6f

typedef __nv_bfloat16 bf16;

// Scratch (allocation-free rule: __device__ globals)
__device__ float g_hn [BATCH * CH * HW];
__device__ bf16  g_hnt[BATCH * CH * HW];                 // [HW, C]
__device__ bf16  g_qk [BATCH * HW * 2 * CH];             // [HW, 1024] q|k
__device__ bf16  g_v  [BATCH * CH * HW];                 // [C, HW]
__device__ bf16  g_aot[BATCH * CH * HW];                 // [HW, C]
__device__ float g_s  [(size_t)BATCH * HW * HW];         // fp32 scores
__device__ bf16  g_attn[(size_t)BATCH * HW * HW];        // bf16 attn
__device__ bf16  g_wb [4 * CH * CH];                     // bf16 weights q,k,v,o
__device__ float g_b2 [2 * CH];                          // bias concat bq|bk

// ---------------------------------------------------------------------------
// helpers
// ---------------------------------------------------------------------------
__device__ __forceinline__ uint32_t smem_u32(const void* p) {
    uint32_t a;
    asm("{ .reg .u64 t; cvta.to.shared.u64 t, %1; cvt.u32.u64 %0, t; }"
        : "=r"(a) : "l"(p));
    return a;
}
__device__ __forceinline__ uint32_t lds32(uint32_t a) {
    uint32_t v;
    asm("ld.shared.b32 %0, [%1];" : "=r"(v) : "r"(a));
    return v;
}
__device__ __forceinline__ uint32_t pack_bf2(float a, float b) {
    __nv_bfloat162 h = __floats2bfloat162_rn(a, b);
    return *(uint32_t*)&h;
}
#define CP_ASYNC16(saddr, gaddr) \
    asm volatile("cp.async.cg.shared.global [%0], [%1], 16;" \
                 :: "r"(saddr), "l"(gaddr) : "memory")
#define CP_COMMIT() asm volatile("cp.async.commit_group;" ::: "memory")
#define CP_WAIT0()  asm volatile("cp.async.wait_group 0;"  ::: "memory")
#define CP_WAIT1()  asm volatile("cp.async.wait_group 1;"  ::: "memory")

__device__ __forceinline__ void mma16(float (&d)[4], const uint32_t (&a)[4],
                                      const uint32_t (&b)[2]) {
    asm volatile(
        "mma.sync.aligned.m16n8k16.row.col.f32.bf16.bf16.f32 "
        "{%0,%1,%2,%3}, {%4,%5,%6,%7}, {%8,%9}, {%0,%1,%2,%3};"
        : "+f"(d[0]), "+f"(d[1]), "+f"(d[2]), "+f"(d[3])
        : "r"(a[0]), "r"(a[1]), "r"(a[2]), "r"(a[3]), "r"(b[0]), "r"(b[1]));
}

// ---------------------------------------------------------------------------
// Pre-convert weights to bf16 (q,k,v,o) and concat bq|bk
// ---------------------------------------------------------------------------
__global__ __launch_bounds__(256) void prep_kernel(
    const float* __restrict__ w0, const float* __restrict__ w1,
    const float* __restrict__ w2, const float* __restrict__ w3,
    const float* __restrict__ bq, const float* __restrict__ bk,
    bf16* __restrict__ out, float* __restrict__ b2)
{
    const int n4 = CH * CH / 4;
    const int gid = blockIdx.x * 256 + threadIdx.x;
    const int stride = gridDim.x * 256;
    for (int i = gid; i < 4 * n4; i += stride) {
        const int m = i / n4, j = i - m * n4;
        const float* src = (m == 0) ? w0 : (m == 1) ? w1 : (m == 2) ? w2 : w3;
        float4 v = ((const float4*)src)[j];
        uint2 w;
        w.x = pack_bf2(v.x, v.y);
        w.y = pack_bf2(v.z, v.w);
        ((uint2*)out)[i] = w;
    }
    for (int i = gid; i < 2 * CH; i += stride)
        b2[i] = (i < CH) ? bq[i] : bk[i - CH];
}

// ---------------------------------------------------------------------------
// GroupNorm: one block per (group, batch)
// ---------------------------------------------------------------------------
__global__ __launch_bounds__(256) void groupnorm_kernel(
    const float* __restrict__ x, const float* __restrict__ gamma,
    const float* __restrict__ beta, float* __restrict__ out)
{
    const int g = blockIdx.x;
    const int b = blockIdx.y;
    const size_t base = ((size_t)b * CH + g * CPG) * HW;
    const float* xg = x + base;

    float s = 0.f, ss = 0.f;
    for (int i = threadIdx.x; i < CPG * HW; i += 256) {
        float v = xg[i];
        s += v; ss += v * v;
    }
    for (int o = 16; o; o >>= 1) {
        s  += __shfl_xor_sync(0xffffffffu, s,  o);
        ss += __shfl_xor_sync(0xffffffffu, ss, o);
    }
    __shared__ float sw[8], sw2[8];
    const int warp = threadIdx.x >> 5, lane = threadIdx.x & 31;
    if (lane == 0) { sw[warp] = s; sw2[warp] = ss; }
    __syncthreads();
    if (warp == 0) {
        s  = (lane < 8) ? sw[lane]  : 0.f;
        ss = (lane < 8) ? sw2[lane] : 0.f;
        for (int o = 4; o; o >>= 1) {
            s  += __shfl_xor_sync(0xffffffffu, s,  o);
            ss += __shfl_xor_sync(0xffffffffu, ss, o);
        }
        if (lane == 0) {
            const float n    = (float)(CPG * HW);
            const float mean = s / n;
            const float var  = ss / n - mean * mean;
            sw[0]  = mean;
            sw2[0] = rsqrtf(var + EPSV);
        }
    }
    __syncthreads();
    const float mean = sw[0], inv = sw2[0];
    for (int i = threadIdx.x; i < CPG * HW; i += 256) {
        const int c = g * CPG + (i >> 12);
        out[base + i] = (xg[i] - mean) * inv * gamma[c] + beta[c];
    }
}

// ---------------------------------------------------------------------------
// Transpose [C, HW] fp32 -> [HW, C] bf16 per batch
// ---------------------------------------------------------------------------
__global__ __launch_bounds__(256) void transpose_kernel(
    const float* __restrict__ in, bf16* __restrict__ out)
{
    __shared__ float tile[32][33];
    const int b = blockIdx.z;
    in  += (size_t)b * CH * HW;
    out += (size_t)b * CH * HW;
    const int p0 = blockIdx.x * 32, c0 = blockIdx.y * 32;
    const int tx = threadIdx.x & 31, ty = threadIdx.x >> 5;
#pragma unroll
    for (int i = 0; i < 32; i += 8)
        tile[ty + i][tx] = in[(size_t)(c0 + ty + i) * HW + p0 + tx];
    __syncthreads();
#pragma unroll
    for (int i = 0; i < 32; i += 8)
        out[(size_t)(p0 + ty + i) * CH + c0 + tx] =
            __float2bfloat16_rn(tile[tx][ty + i]);
}

// ---------------------------------------------------------------------------
// bf16 mma.sync GEMM: D = scale * A(M,K) . B(N,K)^T  (+epilogue)
// MODE: 0=scale only, 1=+bias[n], 2=+bias[m], 3=+bias[m]+res[m,n]
// OT:   0 -> fp32 output, 1 -> bf16 output
// 128x128 CTA tile, BK=32, 3-stage cp.async, 256 threads, warp tile 64x32.
// smem: row stride 40 bf16 (80B) -> conflict-free frag LDS; stage=10240B.
// ---------------------------------------------------------------------------
#define STG_B 10240
template<int MODE, int OT>
__global__ __launch_bounds__(256, 2) void bgemm(
    const bf16* __restrict__ A, const bf16* __restrict__ B,
    void* __restrict__ Cv,
    const float* __restrict__ bias, const float* __restrict__ res,
    int K, int lda, int ldb, int ldc,
    long long sA, long long sB, long long sC, float scale)
{
    extern __shared__ char sm[];
    const uint32_t Abase = smem_u32(sm);
    const uint32_t Bbase = Abase + 3 * STG_B;

    const int tid = threadIdx.x, lane = tid & 31, wid = tid >> 5;
    const int wm = wid & 1, wn = wid >> 1;          // warp grid 2 x 4
    const int grp = lane >> 2, tig = lane & 3;
    const int bz = blockIdx.z;
    A += bz * sA; B += bz * sB;
    const float* resb = (MODE == 3) ? res + bz * sC : nullptr;
    const int m0 = blockIdx.y * 128, n0 = blockIdx.x * 128;

    // cp.async mapping: thread -> rows (tid>>2, +64), 16B chunk (tid&3)
    const int lr = tid >> 2;
    const int lc8 = (tid & 3) * 8;                  // bf16 col offset
    const bf16* Ag0 = A + (size_t)(m0 + lr) * lda + lc8;
    const bf16* Ag1 = Ag0 + (size_t)64 * lda;
    const bf16* Bg0 = B + (size_t)(n0 + lr) * ldb + lc8;
    const bf16* Bg1 = Bg0 + (size_t)64 * ldb;
    const uint32_t sa0 = Abase + (uint32_t)(lr * 80 + (tid & 3) * 16);
    const uint32_t sb0 = Bbase + (uint32_t)(lr * 80 + (tid & 3) * 16);
    const uint32_t roff = 64 * 80;                  // +64 rows (bytes)

    // frag base addresses (bytes)
    const uint32_t fa0 = Abase + (uint32_t)((wm * 64 + grp) * 80 + tig * 4);
    const uint32_t fb0 = Bbase + (uint32_t)((wn * 32 + grp) * 80 + tig * 4);

    float acc[4][4][4];
#pragma unroll
    for (int mt = 0; mt < 4; mt++)
#pragma unroll
        for (int nt = 0; nt < 4; nt++)
#pragma unroll
            for (int j = 0; j < 4; j++) acc[mt][nt][j] = 0.f;

    const int T = K >> 5;           // BK=32

    // prologue: stages 0,1
#pragma unroll
    for (int p = 0; p < 2; p++) {
        const size_t ko = (size_t)p * 32;
        CP_ASYNC16(sa0 + p * STG_B,        Ag0 + ko);
        CP_ASYNC16(sa0 + p * STG_B + roff, Ag1 + ko);
        CP_ASYNC16(sb0 + p * STG_B,        Bg0 + ko);
        CP_ASYNC16(sb0 + p * STG_B + roff, Bg1 + ko);
        CP_COMMIT();
    }

    int cur = 0, nxt_issue = 2;
    for (int kt = 0; kt < T; kt++) {
        if (kt + 1 < T) CP_WAIT1(); else CP_WAIT0();
        __syncthreads();

        const uint32_t fa = fa0 + cur * STG_B;
        const uint32_t fb = fb0 + cur * STG_B;
#pragma unroll
        for (int kk = 0; kk < 2; kk++) {          // two k16 steps per tile
            const uint32_t ko = kk * 32;          // 16 bf16 = 32 bytes
            uint32_t af[4][4], bf[4][2];
#pragma unroll
            for (int mt = 0; mt < 4; mt++) {
                const uint32_t a = fa + mt * (16 * 80) + ko;
                af[mt][0] = lds32(a);
                af[mt][1] = lds32(a + 8 * 80);
                af[mt][2] = lds32(a + 16);
                af[mt][3] = lds32(a + 8 * 80 + 16);
            }
#pragma unroll
            for (int nt = 0; nt < 4; nt++) {
                const uint32_t b = fb + nt * (8 * 80) + ko;
                bf[nt][0] = lds32(b);
                bf[nt][1] = lds32(b + 16);
            }
#pragma unroll
            for (int mt = 0; mt < 4; mt++)
#pragma unroll
                for (int nt = 0; nt < 4; nt++)
                    mma16(acc[mt][nt], af[mt], bf[nt]);
        }

        if (kt + 2 < T) {
            const size_t ko = (size_t)(kt + 2) * 32;
            const uint32_t st = nxt_issue * STG_B;
            CP_ASYNC16(sa0 + st,        Ag0 + ko);
            CP_ASYNC16(sa0 + st + roff, Ag1 + ko);
            CP_ASYNC16(sb0 + st,        Bg0 + ko);
            CP_ASYNC16(sb0 + st + roff, Bg1 + ko);
            CP_COMMIT();
        }
        cur = (cur + 1 == 3) ? 0 : cur + 1;
        nxt_issue = (nxt_issue + 1 == 3) ? 0 : nxt_issue + 1;
    }

    // Epilogue
    float* Cf = (float*)Cv + ((OT == 0) ? bz * sC : 0);
    bf16*  Cb = (bf16*)Cv  + ((OT == 1) ? bz * sC : 0);
#pragma unroll
    for (int mt = 0; mt < 4; mt++) {
        const int r0 = m0 + wm * 64 + mt * 16 + grp;
        float bm0 = 0.f, bm1 = 0.f;
        if (MODE == 2 || MODE == 3) { bm0 = bias[r0]; bm1 = bias[r0 + 8]; }
#pragma unroll
        for (int nt = 0; nt < 4; nt++) {
            const int c = n0 + wn * 32 + nt * 8 + tig * 2;
            const float* d = acc[mt][nt];
            float2 o0 = { d[0] * scale, d[1] * scale };
            float2 o1 = { d[2] * scale, d[3] * scale };
            if (MODE == 1) {
                const float2 bn = *(const float2*)&bias[c];
                o0.x += bn.x; o0.y += bn.y; o1.x += bn.x; o1.y += bn.y;
            }
            if (MODE == 2 || MODE == 3) {
                o0.x += bm0; o0.y += bm0; o1.x += bm1; o1.y += bm1;
            }
            const size_t i0 = (size_t)r0 * ldc + c;
            const size_t i1 = (size_t)(r0 + 8) * ldc + c;
            if (MODE == 3) {
                const float2 r0v = *(const float2*)&resb[i0];
                const float2 r1v = *(const float2*)&resb[i1];
                o0.x += r0v.x; o0.y += r0v.y; o1.x += r1v.x; o1.y += r1v.y;
            }
            if (OT == 0) {
                *(float2*)&Cf[i0] = o0;
                *(float2*)&Cf[i1] = o1;
            } else {
                *(uint32_t*)&Cb[i0] = pack_bf2(o0.x, o0.y);
                *(uint32_t*)&Cb[i1] = pack_bf2(o1.x, o1.y);
            }
        }
    }
}

// ---------------------------------------------------------------------------
// Row softmax: fp32 scores in -> bf16 attn out
// ---------------------------------------------------------------------------
__global__ __launch_bounds__(256) void softmax_kernel(
    const float* __restrict__ s, bf16* __restrict__ attn)
{
    const float4* p = (const float4*)(s + (size_t)blockIdx.x * HW);
    uint2* po = (uint2*)(attn + (size_t)blockIdx.x * HW);
    const int t = threadIdx.x;
    const int warp = t >> 5, lane = t & 31;
    __shared__ float sh[8];

    float4 v[4];
    float mx = -3.4e38f;
#pragma unroll
    for (int i = 0; i < 4; i++) {
        v[i] = p[t + i * 256];
        mx = fmaxf(mx, fmaxf(fmaxf(v[i].x, v[i].y), fmaxf(v[i].z, v[i].w)));
    }
    for (int o = 16; o; o >>= 1) mx = fmaxf(mx, __shfl_xor_sync(0xffffffffu, mx, o));
    if (lane == 0) sh[warp] = mx;
    __syncthreads();
    if (warp == 0) {
        float m = (lane < 8) ? sh[lane] : -3.4e38f;
        for (int o = 4; o; o >>= 1) m = fmaxf(m, __shfl_xor_sync(0xffffffffu, m, o));
        if (lane == 0) sh[0] = m;
    }
    __syncthreads();
    mx = sh[0];
    __syncthreads();

    float sum = 0.f;
#pragma unroll
    for (int i = 0; i < 4; i++) {
        v[i].x = __expf(v[i].x - mx);
        v[i].y = __expf(v[i].y - mx);
        v[i].z = __expf(v[i].z - mx);
        v[i].w = __expf(v[i].w - mx);
        sum += v[i].x + v[i].y + v[i].z + v[i].w;
    }
    for (int o = 16; o; o >>= 1) sum += __shfl_xor_sync(0xffffffffu, sum, o);
    if (lane == 0) sh[warp] = sum;
    __syncthreads();
    if (warp == 0) {
        float m = (lane < 8) ? sh[lane] : 0.f;
        for (int o = 4; o; o >>= 1) m += __shfl_xor_sync(0xffffffffu, m, o);
        if (lane == 0) sh[0] = m;
    }
    __syncthreads();
    const float inv = 1.0f / sh[0];
#pragma unroll
    for (int i = 0; i < 4; i++) {
        uint2 w;
        w.x = pack_bf2(v[i].x * inv, v[i].y * inv);
        w.y = pack_bf2(v[i].z * inv, v[i].w * inv);
        po[t + i * 256] = w;
    }
}

// ---------------------------------------------------------------------------
extern "C" void kernel_launch(void* const* d_in, const int* in_sizes, int n_in,
                              void* d_out, int out_size)
{
    const float* x     = (const float*)d_in[0];
    const float* gamma = (const float*)d_in[1];
    const float* beta  = (const float*)d_in[2];
    const float* wq    = (const float*)d_in[3];
    const float* bq    = (const float*)d_in[4];
    const float* wk    = (const float*)d_in[5];
    const float* bk    = (const float*)d_in[6];
    const float* wv    = (const float*)d_in[7];
    const float* bv    = (const float*)d_in[8];
    const float* wo    = (const float*)d_in[9];
    const float* bo    = (const float*)d_in[10];
    float* out = (float*)d_out;

    float *hn, *s, *b2;
    bf16 *hnt, *qk, *v, *aot, *attn, *wb;
    cudaGetSymbolAddress((void**)&hn,   g_hn);
    cudaGetSymbolAddress((void**)&hnt,  g_hnt);
    cudaGetSymbolAddress((void**)&qk,   g_qk);
    cudaGetSymbolAddress((void**)&v,    g_v);
    cudaGetSymbolAddress((void**)&aot,  g_aot);
    cudaGetSymbolAddress((void**)&s,    g_s);
    cudaGetSymbolAddress((void**)&attn, g_attn);
    cudaGetSymbolAddress((void**)&wb,   g_wb);
    cudaGetSymbolAddress((void**)&b2,   g_b2);
    const bf16* wvb = wb + 2 * CH * CH;
    const bf16* wob = wb + 3 * CH * CH;

    const int SMEM = 6 * STG_B;       // 61440 B
    static int smem_set = 0;
    if (!smem_set) {
        cudaFuncSetAttribute(bgemm<1,1>, cudaFuncAttributeMaxDynamicSharedMemorySize, SMEM);
        cudaFuncSetAttribute(bgemm<2,1>, cudaFuncAttributeMaxDynamicSharedMemorySize, SMEM);
        cudaFuncSetAttribute(bgemm<0,0>, cudaFuncAttributeMaxDynamicSharedMemorySize, SMEM);
        cudaFuncSetAttribute(bgemm<0,1>, cudaFuncAttributeMaxDynamicSharedMemorySize, SMEM);
        cudaFuncSetAttribute(bgemm<3,0>, cudaFuncAttributeMaxDynamicSharedMemorySize, SMEM);
        smem_set = 1;
    }

    const long long sCH  = (long long)CH * HW;
    const long long sQK  = (long long)HW * 2 * CH;
    const long long sHW  = (long long)HW * HW;
    const float scale = 0.044194173824159216f;   // 1/sqrt(512)

    // 0. weights -> bf16, bias concat
    prep_kernel<<<256, 256>>>(wq, wk, wv, wo, bq, bk, wb, b2);
    // 1. GroupNorm -> hn [C, HW] fp32
    groupnorm_kernel<<<dim3(NG, BATCH), 256>>>(x, gamma, beta, hn);
    // 2. hn -> hnt [HW, C] bf16
    transpose_kernel<<<dim3(HW / 32, CH / 32, BATCH), 256>>>(hn, hnt);

    // 3. qk[p, 0:1024] = hnt . [Wq;Wk]^T + [bq;bk]   (M=4096, N=1024, K=512)
    bgemm<1,1><<<dim3(2 * CH / 128, HW / 128, BATCH), 256, SMEM>>>(
        hnt, wb, qk, b2, nullptr, CH, CH, CH, 2 * CH, sCH, 0, sQK, 1.f);
    // 4. v[c,p] = Wv . hnt^T + bv[c]                 (M=512, N=4096, K=512)
    bgemm<2,1><<<dim3(HW / 128, CH / 128, BATCH), 256, SMEM>>>(
        wvb, hnt, v, bv, nullptr, CH, CH, CH, HW, 0, sCH, sCH, 1.f);

    // 5. s[i,j] = (q . k^T) * scale                  (M=4096, N=4096, K=512)
    bgemm<0,0><<<dim3(HW / 128, HW / 128, BATCH), 256, SMEM>>>(
        qk, qk + CH, s, nullptr, nullptr, CH, 2 * CH, 2 * CH, HW, sQK, sQK, sHW, scale);

    // 6. softmax rows -> bf16 attn
    softmax_kernel<<<BATCH * HW, 256>>>(s, attn);

    // 7. ao_t[i,c] = attn . v^T                      (M=4096, N=512, K=4096)
    bgemm<0,1><<<dim3(CH / 128, HW / 128, BATCH), 256, SMEM>>>(
        attn, v, aot, nullptr, nullptr, HW, HW, HW, CH, sHW, sCH, sCH, 1.f);

    // 8. out[o,p] = Wo . ao_t^T + bo[o] + x          (M=512, N=4096, K=512)
    bgemm<3,0><<<dim3(HW / 128, CH / 128, BATCH), 256, SMEM>>>(
        wob, aot, out, bo, x, CH, CH, CH, HW, 0, sCH, sCH, 1.f);
}

// round 9
// speedup vs baseline: 6.1618x; 1.0969x over previous
#include <cuda_runtime.h>
#include <cuda_bf16.h>
#include <cstdint>

#define CH 512
#define HW 4096
#define BATCH 2
#define NG 32
#define CPG 16
#define EPSV 1e-6f

typedef __nv_bfloat16 bf16;

// Scratch (allocation-free rule: __device__ globals)
__device__ float g_hn [BATCH * CH * HW];
__device__ bf16  g_hnt[BATCH * CH * HW];                 // [HW, C]
__device__ bf16  g_qk [BATCH * HW * 2 * CH];             // [HW, 1024] q|k
__device__ bf16  g_v  [BATCH * CH * HW];                 // [C, HW]
__device__ bf16  g_aot[BATCH * CH * HW];                 // [HW, C]
__device__ float g_s  [(size_t)BATCH * HW * HW];         // fp32 scores
__device__ bf16  g_attn[(size_t)BATCH * HW * HW];        // bf16 attn
__device__ bf16  g_wb [4 * CH * CH];                     // bf16 weights q,k,v,o
__device__ float g_b2 [2 * CH];                          // bias concat bq|bk

// ---------------------------------------------------------------------------
// helpers
// ---------------------------------------------------------------------------
__device__ __forceinline__ uint32_t smem_u32(const void* p) {
    uint32_t a;
    asm("{ .reg .u64 t; cvta.to.shared.u64 t, %1; cvt.u32.u64 %0, t; }"
        : "=r"(a) : "l"(p));
    return a;
}
__device__ __forceinline__ uint32_t pack_bf2(float a, float b) {
    __nv_bfloat162 h = __floats2bfloat162_rn(a, b);
    return *(uint32_t*)&h;
}
#define CP_ASYNC16(saddr, gaddr) \
    asm volatile("cp.async.cg.shared.global [%0], [%1], 16;" \
                 :: "r"(saddr), "l"(gaddr) : "memory")
#define CP_COMMIT() asm volatile("cp.async.commit_group;" ::: "memory")
#define CP_WAIT0()  asm volatile("cp.async.wait_group 0;"  ::: "memory")
#define CP_WAIT1()  asm volatile("cp.async.wait_group 1;"  ::: "memory")

#define LDSM4(r0, r1, r2, r3, addr) \
    asm volatile("ldmatrix.sync.aligned.m8n8.x4.shared.b16 {%0,%1,%2,%3}, [%4];" \
                 : "=r"(r0), "=r"(r1), "=r"(r2), "=r"(r3) : "r"(addr))

__device__ __forceinline__ void mma16(float (&d)[4], const uint32_t (&a)[4],
                                      const uint32_t (&b)[2]) {
    asm volatile(
        "mma.sync.aligned.m16n8k16.row.col.f32.bf16.bf16.f32 "
        "{%0,%1,%2,%3}, {%4,%5,%6,%7}, {%8,%9}, {%0,%1,%2,%3};"
        : "+f"(d[0]), "+f"(d[1]), "+f"(d[2]), "+f"(d[3])
        : "r"(a[0]), "r"(a[1]), "r"(a[2]), "r"(a[3]), "r"(b[0]), "r"(b[1]));
}

// ---------------------------------------------------------------------------
// Pre-convert weights to bf16 (q,k,v,o) and concat bq|bk
// ---------------------------------------------------------------------------
__global__ __launch_bounds__(256) void prep_kernel(
    const float* __restrict__ w0, const float* __restrict__ w1,
    const float* __restrict__ w2, const float* __restrict__ w3,
    const float* __restrict__ bq, const float* __restrict__ bk,
    bf16* __restrict__ out, float* __restrict__ b2)
{
    const int n4 = CH * CH / 4;
    const int gid = blockIdx.x * 256 + threadIdx.x;
    const int stride = gridDim.x * 256;
    for (int i = gid; i < 4 * n4; i += stride) {
        const int m = i / n4, j = i - m * n4;
        const float* src = (m == 0) ? w0 : (m == 1) ? w1 : (m == 2) ? w2 : w3;
        float4 v = ((const float4*)src)[j];
        uint2 w;
        w.x = pack_bf2(v.x, v.y);
        w.y = pack_bf2(v.z, v.w);
        ((uint2*)out)[i] = w;
    }
    for (int i = gid; i < 2 * CH; i += stride)
        b2[i] = (i < CH) ? bq[i] : bk[i - CH];
}

// ---------------------------------------------------------------------------
// GroupNorm: one block per (group, batch)
// ---------------------------------------------------------------------------
__global__ __launch_bounds__(256) void groupnorm_kernel(
    const float* __restrict__ x, const float* __restrict__ gamma,
    const float* __restrict__ beta, float* __restrict__ out)
{
    const int g = blockIdx.x;
    const int b = blockIdx.y;
    const size_t base = ((size_t)b * CH + g * CPG) * HW;
    const float* xg = x + base;

    float s = 0.f, ss = 0.f;
    for (int i = threadIdx.x; i < CPG * HW; i += 256) {
        float v = xg[i];
        s += v; ss += v * v;
    }
    for (int o = 16; o; o >>= 1) {
        s  += __shfl_xor_sync(0xffffffffu, s,  o);
        ss += __shfl_xor_sync(0xffffffffu, ss, o);
    }
    __shared__ float sw[8], sw2[8];
    const int warp = threadIdx.x >> 5, lane = threadIdx.x & 31;
    if (lane == 0) { sw[warp] = s; sw2[warp] = ss; }
    __syncthreads();
    if (warp == 0) {
        s  = (lane < 8) ? sw[lane]  : 0.f;
        ss = (lane < 8) ? sw2[lane] : 0.f;
        for (int o = 4; o; o >>= 1) {
            s  += __shfl_xor_sync(0xffffffffu, s,  o);
            ss += __shfl_xor_sync(0xffffffffu, ss, o);
        }
        if (lane == 0) {
            const float n    = (float)(CPG * HW);
            const float mean = s / n;
            const float var  = ss / n - mean * mean;
            sw[0]  = mean;
            sw2[0] = rsqrtf(var + EPSV);
        }
    }
    __syncthreads();
    const float mean = sw[0], inv = sw2[0];
    for (int i = threadIdx.x; i < CPG * HW; i += 256) {
        const int c = g * CPG + (i >> 12);
        out[base + i] = (xg[i] - mean) * inv * gamma[c] + beta[c];
    }
}

// ---------------------------------------------------------------------------
// Transpose [C, HW] fp32 -> [HW, C] bf16 per batch
// ---------------------------------------------------------------------------
__global__ __launch_bounds__(256) void transpose_kernel(
    const float* __restrict__ in, bf16* __restrict__ out)
{
    __shared__ float tile[32][33];
    const int b = blockIdx.z;
    in  += (size_t)b * CH * HW;
    out += (size_t)b * CH * HW;
    const int p0 = blockIdx.x * 32, c0 = blockIdx.y * 32;
    const int tx = threadIdx.x & 31, ty = threadIdx.x >> 5;
#pragma unroll
    for (int i = 0; i < 32; i += 8)
        tile[ty + i][tx] = in[(size_t)(c0 + ty + i) * HW + p0 + tx];
    __syncthreads();
#pragma unroll
    for (int i = 0; i < 32; i += 8)
        out[(size_t)(p0 + ty + i) * CH + c0 + tx] =
            __float2bfloat16_rn(tile[tx][ty + i]);
}

// ---------------------------------------------------------------------------
// bf16 mma.sync GEMM: D = scale * A(M,K) . B(N,K)^T  (+epilogue)
// MODE: 0=scale only, 1=+bias[n], 2=+bias[m], 3=+bias[m]+res[m,n]
// OT:   0 -> fp32 output, 1 -> bf16 output
// 128x128 CTA tile, BK=32, 3-stage cp.async, 256 threads, warp tile 64x32.
// smem row stride 80B: conflict-free for both cp.async stores and ldmatrix.
// ---------------------------------------------------------------------------
#define STG_B 10240
template<int MODE, int OT>
__global__ __launch_bounds__(256, 2) void bgemm(
    const bf16* __restrict__ A, const bf16* __restrict__ B,
    void* __restrict__ Cv,
    const float* __restrict__ bias, const float* __restrict__ res,
    int K, int lda, int ldb, int ldc,
    long long sA, long long sB, long long sC, float scale)
{
    extern __shared__ char sm[];
    const uint32_t Abase = smem_u32(sm);
    const uint32_t Bbase = Abase + 3 * STG_B;

    const int tid = threadIdx.x, lane = tid & 31, wid = tid >> 5;
    const int wm = wid & 1, wn = wid >> 1;          // warp grid 2 x 4
    const int grp = lane >> 2, tig = lane & 3;
    const int bz = blockIdx.z;
    A += bz * sA; B += bz * sB;
    const float* resb = (MODE == 3) ? res + bz * sC : nullptr;
    const int m0 = blockIdx.y * 128, n0 = blockIdx.x * 128;

    // cp.async mapping: thread -> rows (tid>>2, +64), 16B chunk (tid&3)
    const int lr = tid >> 2;
    const int lc8 = (tid & 3) * 8;                  // bf16 col offset
    const bf16* Ag0 = A + (size_t)(m0 + lr) * lda + lc8;
    const bf16* Ag1 = Ag0 + (size_t)64 * lda;
    const bf16* Bg0 = B + (size_t)(n0 + lr) * ldb + lc8;
    const bf16* Bg1 = Bg0 + (size_t)64 * ldb;
    const uint32_t sa0 = Abase + (uint32_t)(lr * 80 + (tid & 3) * 16);
    const uint32_t sb0 = Bbase + (uint32_t)(lr * 80 + (tid & 3) * 16);
    const uint32_t roff = 64 * 80;                  // +64 rows (bytes)

    // ldmatrix lane addresses (within stage 0):
    // A (4 slabs of 16 rows): x4 -> a0(rows0-7,k0-7) a1(rows8-15,k0-7)
    //                                a2(rows0-7,k8-15) a3(rows8-15,k8-15)
    const uint32_t la_row = lane & 15, la_k = (lane >> 4) * 16;
    uint32_t aaddr[4];
#pragma unroll
    for (int mt = 0; mt < 4; mt++)
        aaddr[mt] = Abase + (uint32_t)((wm * 64 + mt * 16 + la_row) * 80) + la_k;
    // B (2 slabs of 16 rows = 2 n8 tiles each): x4 -> b0(nt) b1(nt) b0(nt+1) b1(nt+1)
    const uint32_t lb_row = ((lane >> 4) * 8) + (lane & 7);
    const uint32_t lb_k = ((lane >> 3) & 1) * 16;
    uint32_t baddr[2];
#pragma unroll
    for (int h = 0; h < 2; h++)
        baddr[h] = Bbase + (uint32_t)((wn * 32 + h * 16 + lb_row) * 80) + lb_k;

    float acc[4][4][4];
#pragma unroll
    for (int mt = 0; mt < 4; mt++)
#pragma unroll
        for (int nt = 0; nt < 4; nt++)
#pragma unroll
            for (int j = 0; j < 4; j++) acc[mt][nt][j] = 0.f;

    const int T = K >> 5;           // BK=32

    // prologue: stages 0,1
#pragma unroll
    for (int p = 0; p < 2; p++) {
        const size_t ko = (size_t)p * 32;
        CP_ASYNC16(sa0 + p * STG_B,        Ag0 + ko);
        CP_ASYNC16(sa0 + p * STG_B + roff, Ag1 + ko);
        CP_ASYNC16(sb0 + p * STG_B,        Bg0 + ko);
        CP_ASYNC16(sb0 + p * STG_B + roff, Bg1 + ko);
        CP_COMMIT();
    }

    int cur = 0, nxt_issue = 2;
    for (int kt = 0; kt < T; kt++) {
        if (kt + 1 < T) CP_WAIT1(); else CP_WAIT0();
        __syncthreads();

        const uint32_t stg = cur * STG_B;
#pragma unroll
        for (int kk = 0; kk < 2; kk++) {          // two k16 steps per tile
            const uint32_t ko = stg + kk * 32;    // 16 bf16 = 32 bytes
            uint32_t af[4][4], bf[4][2];
#pragma unroll
            for (int mt = 0; mt < 4; mt++)
                LDSM4(af[mt][0], af[mt][1], af[mt][2], af[mt][3], aaddr[mt] + ko);
#pragma unroll
            for (int h = 0; h < 2; h++)
                LDSM4(bf[2*h][0], bf[2*h][1], bf[2*h+1][0], bf[2*h+1][1],
                      baddr[h] + ko);
#pragma unroll
            for (int mt = 0; mt < 4; mt++)
#pragma unroll
                for (int nt = 0; nt < 4; nt++)
                    mma16(acc[mt][nt], af[mt], bf[nt]);
        }

        if (kt + 2 < T) {
            const size_t ko = (size_t)(kt + 2) * 32;
            const uint32_t st = nxt_issue * STG_B;
            CP_ASYNC16(sa0 + st,        Ag0 + ko);
            CP_ASYNC16(sa0 + st + roff, Ag1 + ko);
            CP_ASYNC16(sb0 + st,        Bg0 + ko);
            CP_ASYNC16(sb0 + st + roff, Bg1 + ko);
            CP_COMMIT();
        }
        cur = (cur + 1 == 3) ? 0 : cur + 1;
        nxt_issue = (nxt_issue + 1 == 3) ? 0 : nxt_issue + 1;
    }

    // Epilogue
    float* Cf = (float*)Cv + ((OT == 0) ? bz * sC : 0);
    bf16*  Cb = (bf16*)Cv  + ((OT == 1) ? bz * sC : 0);
#pragma unroll
    for (int mt = 0; mt < 4; mt++) {
        const int r0 = m0 + wm * 64 + mt * 16 + grp;
        float bm0 = 0.f, bm1 = 0.f;
        if (MODE == 2 || MODE == 3) { bm0 = bias[r0]; bm1 = bias[r0 + 8]; }
#pragma unroll
        for (int nt = 0; nt < 4; nt++) {
            const int c = n0 + wn * 32 + nt * 8 + tig * 2;
            const float* d = acc[mt][nt];
            float2 o0 = { d[0] * scale, d[1] * scale };
            float2 o1 = { d[2] * scale, d[3] * scale };
            if (MODE == 1) {
                const float2 bn = *(const float2*)&bias[c];
                o0.x += bn.x; o0.y += bn.y; o1.x += bn.x; o1.y += bn.y;
            }
            if (MODE == 2 || MODE == 3) {
                o0.x += bm0; o0.y += bm0; o1.x += bm1; o1.y += bm1;
            }
            const size_t i0 = (size_t)r0 * ldc + c;
            const size_t i1 = (size_t)(r0 + 8) * ldc + c;
            if (MODE == 3) {
                const float2 r0v = *(const float2*)&resb[i0];
                const float2 r1v = *(const float2*)&resb[i1];
                o0.x += r0v.x; o0.y += r0v.y; o1.x += r1v.x; o1.y += r1v.y;
            }
            if (OT == 0) {
                *(float2*)&Cf[i0] = o0;
                *(float2*)&Cf[i1] = o1;
            } else {
                *(uint32_t*)&Cb[i0] = pack_bf2(o0.x, o0.y);
                *(uint32_t*)&Cb[i1] = pack_bf2(o1.x, o1.y);
            }
        }
    }
}

// ---------------------------------------------------------------------------
// Row softmax: fp32 scores in -> bf16 attn out
// ---------------------------------------------------------------------------
__global__ __launch_bounds__(256) void softmax_kernel(
    const float* __restrict__ s, bf16* __restrict__ attn)
{
    const float4* p = (const float4*)(s + (size_t)blockIdx.x * HW);
    uint2* po = (uint2*)(attn + (size_t)blockIdx.x * HW);
    const int t = threadIdx.x;
    const int warp = t >> 5, lane = t & 31;
    __shared__ float sh[8];

    float4 v[4];
    float mx = -3.4e38f;
#pragma unroll
    for (int i = 0; i < 4; i++) {
        v[i] = p[t + i * 256];
        mx = fmaxf(mx, fmaxf(fmaxf(v[i].x, v[i].y), fmaxf(v[i].z, v[i].w)));
    }
    for (int o = 16; o; o >>= 1) mx = fmaxf(mx, __shfl_xor_sync(0xffffffffu, mx, o));
    if (lane == 0) sh[warp] = mx;
    __syncthreads();
    if (warp == 0) {
        float m = (lane < 8) ? sh[lane] : -3.4e38f;
        for (int o = 4; o; o >>= 1) m = fmaxf(m, __shfl_xor_sync(0xffffffffu, m, o));
        if (lane == 0) sh[0] = m;
    }
    __syncthreads();
    mx = sh[0];
    __syncthreads();

    float sum = 0.f;
#pragma unroll
    for (int i = 0; i < 4; i++) {
        v[i].x = __expf(v[i].x - mx);
        v[i].y = __expf(v[i].y - mx);
        v[i].z = __expf(v[i].z - mx);
        v[i].w = __expf(v[i].w - mx);
        sum += v[i].x + v[i].y + v[i].z + v[i].w;
    }
    for (int o = 16; o; o >>= 1) sum += __shfl_xor_sync(0xffffffffu, sum, o);
    if (lane == 0) sh[warp] = sum;
    __syncthreads();
    if (warp == 0) {
        float m = (lane < 8) ? sh[lane] : 0.f;
        for (int o = 4; o; o >>= 1) m += __shfl_xor_sync(0xffffffffu, m, o);
        if (lane == 0) sh[0] = m;
    }
    __syncthreads();
    const float inv = 1.0f / sh[0];
#pragma unroll
    for (int i = 0; i < 4; i++) {
        uint2 w;
        w.x = pack_bf2(v[i].x * inv, v[i].y * inv);
        w.y = pack_bf2(v[i].z * inv, v[i].w * inv);
        po[t + i * 256] = w;
    }
}

// ---------------------------------------------------------------------------
extern "C" void kernel_launch(void* const* d_in, const int* in_sizes, int n_in,
                              void* d_out, int out_size)
{
    const float* x     = (const float*)d_in[0];
    const float* gamma = (const float*)d_in[1];
    const float* beta  = (const float*)d_in[2];
    const float* wq    = (const float*)d_in[3];
    const float* bq    = (const float*)d_in[4];
    const float* wk    = (const float*)d_in[5];
    const float* bk    = (const float*)d_in[6];
    const float* wv    = (const float*)d_in[7];
    const float* bv    = (const float*)d_in[8];
    const float* wo    = (const float*)d_in[9];
    const float* bo    = (const float*)d_in[10];
    float* out = (float*)d_out;

    float *hn, *s, *b2;
    bf16 *hnt, *qk, *v, *aot, *attn, *wb;
    cudaGetSymbolAddress((void**)&hn,   g_hn);
    cudaGetSymbolAddress((void**)&hnt,  g_hnt);
    cudaGetSymbolAddress((void**)&qk,   g_qk);
    cudaGetSymbolAddress((void**)&v,    g_v);
    cudaGetSymbolAddress((void**)&aot,  g_aot);
    cudaGetSymbolAddress((void**)&s,    g_s);
    cudaGetSymbolAddress((void**)&attn, g_attn);
    cudaGetSymbolAddress((void**)&wb,   g_wb);
    cudaGetSymbolAddress((void**)&b2,   g_b2);
    const bf16* wvb = wb + 2 * CH * CH;
    const bf16* wob = wb + 3 * CH * CH;

    const int SMEM = 6 * STG_B;       // 61440 B
    static int smem_set = 0;
    if (!smem_set) {
        cudaFuncSetAttribute(bgemm<1,1>, cudaFuncAttributeMaxDynamicSharedMemorySize, SMEM);
        cudaFuncSetAttribute(bgemm<2,1>, cudaFuncAttributeMaxDynamicSharedMemorySize, SMEM);
        cudaFuncSetAttribute(bgemm<0,0>, cudaFuncAttributeMaxDynamicSharedMemorySize, SMEM);
        cudaFuncSetAttribute(bgemm<0,1>, cudaFuncAttributeMaxDynamicSharedMemorySize, SMEM);
        cudaFuncSetAttribute(bgemm<3,0>, cudaFuncAttributeMaxDynamicSharedMemorySize, SMEM);
        smem_set = 1;
    }

    const long long sCH  = (long long)CH * HW;
    const long long sQK  = (long long)HW * 2 * CH;
    const long long sHW  = (long long)HW * HW;
    const float scale = 0.044194173824159216f;   // 1/sqrt(512)

    // 0. weights -> bf16, bias concat
    prep_kernel<<<256, 256>>>(wq, wk, wv, wo, bq, bk, wb, b2);
    // 1. GroupNorm -> hn [C, HW] fp32
    groupnorm_kernel<<<dim3(NG, BATCH), 256>>>(x, gamma, beta, hn);
    // 2. hn -> hnt [HW, C] bf16
    transpose_kernel<<<dim3(HW / 32, CH / 32, BATCH), 256>>>(hn, hnt);

    // 3. qk[p, 0:1024] = hnt . [Wq;Wk]^T + [bq;bk]   (M=4096, N=1024, K=512)
    bgemm<1,1><<<dim3(2 * CH / 128, HW / 128, BATCH), 256, SMEM>>>(
        hnt, wb, qk, b2, nullptr, CH, CH, CH, 2 * CH, sCH, 0, sQK, 1.f);
    // 4. v[c,p] = Wv . hnt^T + bv[c]                 (M=512, N=4096, K=512)
    bgemm<2,1><<<dim3(HW / 128, CH / 128, BATCH), 256, SMEM>>>(
        wvb, hnt, v, bv, nullptr, CH, CH, CH, HW, 0, sCH, sCH, 1.f);

    // 5. s[i,j] = (q . k^T) * scale                  (M=4096, N=4096, K=512)
    bgemm<0,0><<<dim3(HW / 128, HW / 128, BATCH), 256, SMEM>>>(
        qk, qk + CH, s, nullptr, nullptr, CH, 2 * CH, 2 * CH, HW, sQK, sQK, sHW, scale);

    // 6. softmax rows -> bf16 attn
    softmax_kernel<<<BATCH * HW, 256>>>(s, attn);

    // 7. ao_t[i,c] = attn . v^T                      (M=4096, N=512, K=4096)
    bgemm<0,1><<<dim3(CH / 128, HW / 128, BATCH), 256, SMEM>>>(
        attn, v, aot, nullptr, nullptr, HW, HW, HW, CH, sHW, sCH, sCH, 1.f);

    // 8. out[o,p] = Wo . ao_t^T + bo[o] + x          (M=512, N=4096, K=512)
    bgemm<3,0><<<dim3(HW / 128, CH / 128, BATCH), 256, SMEM>>>(
        wob, aot, out, bo, x, CH, CH, CH, HW, 0, sCH, sCH, 1.f);
}